// round 1
// baseline (speedup 1.0000x reference)
#include <cuda_runtime.h>
#include <math.h>
#include <stdint.h>

// Problem constants
#define BB      8
#define LL      1024
#define DD      640
#define HH      10
#define DHH     64
#define FFD     1280
#define NLAYERS 6
#define MTOK    (BB * LL)      // 8192 tokens
#define QT      32             // queries per attention block
#define KW      160            // key window per block (QT + 2*64)

// ---------------------------------------------------------------------------
// Scratch (static device allocations — no cudaMalloc allowed)
// ---------------------------------------------------------------------------
__device__ float g_h   [MTOK * DD];       // hidden state       (21 MB)
__device__ float g_qkv [MTOK * 3 * DD];   // qkv                (63 MB)
__device__ float g_t1  [MTOK * FFD];      // o-proj / ff1       (42 MB)
__device__ float g_t2  [MTOK * DD];       // attn out / ff2     (21 MB)
__device__ float g_pp  [BB * 16 * DD];    // pooling partials
__device__ float g_pool[BB * DD];
__device__ float g_ex  [BB * DD];
__device__ float g_ey  [BB * DD];

// ---------------------------------------------------------------------------
// GEMM: C[M,N] = A[M,K] @ W[N,K]^T + bias, optional ReLU.
// BM=128, BN=64, BK=16, 256 threads, 8x4 micro-tile per thread.
// All M,N,K used are multiples of 128/64/16 respectively.
// ---------------------------------------------------------------------------
__global__ __launch_bounds__(256) void gemm_kernel(
    const float* __restrict__ A, const float* __restrict__ W,
    const float* __restrict__ bias, float* __restrict__ C,
    int M, int N, int K, int relu)
{
    __shared__ float As[16][132];   // [k][m], padded stride (528B, 16B aligned)
    __shared__ float Bs[16][68];    // [k][n], padded stride (272B, 16B aligned)

    const int tid = threadIdx.x;
    const int bm  = blockIdx.y * 128;
    const int bn  = blockIdx.x * 64;
    const int tx  = tid & 15;       // N dir, 4 cols each
    const int ty  = tid >> 4;       // M dir, 8 rows each
    const int lrow = tid >> 2;      // 0..63 loader row
    const int lc   = (tid & 3) << 2; // 0,4,8,12 loader k-offset

    float acc[8][4];
    #pragma unroll
    for (int i = 0; i < 8; i++)
        #pragma unroll
        for (int j = 0; j < 4; j++) acc[i][j] = 0.f;

    const float* Abase = A + (size_t)bm * K;
    const float* Wbase = W + (size_t)bn * K;

    for (int k0 = 0; k0 < K; k0 += 16) {
        #pragma unroll
        for (int r = 0; r < 2; r++) {
            int row = lrow + r * 64;
            float4 v = *(const float4*)(Abase + (size_t)row * K + k0 + lc);
            As[lc + 0][row] = v.x; As[lc + 1][row] = v.y;
            As[lc + 2][row] = v.z; As[lc + 3][row] = v.w;
        }
        {
            float4 v = *(const float4*)(Wbase + (size_t)lrow * K + k0 + lc);
            Bs[lc + 0][lrow] = v.x; Bs[lc + 1][lrow] = v.y;
            Bs[lc + 2][lrow] = v.z; Bs[lc + 3][lrow] = v.w;
        }
        __syncthreads();

        #pragma unroll
        for (int kk = 0; kk < 16; kk++) {
            float4 a0 = *(const float4*)&As[kk][ty * 8];
            float4 a1 = *(const float4*)&As[kk][ty * 8 + 4];
            float4 b0 = *(const float4*)&Bs[kk][tx * 4];
            float af[8] = {a0.x, a0.y, a0.z, a0.w, a1.x, a1.y, a1.z, a1.w};
            float bf[4] = {b0.x, b0.y, b0.z, b0.w};
            #pragma unroll
            for (int i = 0; i < 8; i++)
                #pragma unroll
                for (int j = 0; j < 4; j++)
                    acc[i][j] = fmaf(af[i], bf[j], acc[i][j]);
        }
        __syncthreads();
    }

    #pragma unroll
    for (int i = 0; i < 8; i++) {
        int row = bm + ty * 8 + i;
        int col = bn + tx * 4;
        float4 o;
        o.x = acc[i][0] + bias[col + 0];
        o.y = acc[i][1] + bias[col + 1];
        o.z = acc[i][2] + bias[col + 2];
        o.w = acc[i][3] + bias[col + 3];
        if (relu) {
            o.x = fmaxf(o.x, 0.f); o.y = fmaxf(o.y, 0.f);
            o.z = fmaxf(o.z, 0.f); o.w = fmaxf(o.w, 0.f);
        }
        *(float4*)(C + (size_t)row * N + col) = o;
    }
}

// ---------------------------------------------------------------------------
// Banded attention. Block = (qtile of 32, head, batch). 256 threads.
// Keys window: [l0-64, l0+95] (160 keys). Softmax over |q-k|<=64 only —
// matches reference since masked scores get -1e9 (exp underflows to 0).
// Dynamic smem layout (floats):
//   Qs[32][65] | Ks[160][65] | Vs[160][65] | P[32][168] | red[32][8]
// ---------------------------------------------------------------------------
#define ATTN_SMEM_FLOATS (32*65 + 2*160*65 + 32*168 + 32*8)  // 28512
#define ATTN_SMEM_BYTES  (ATTN_SMEM_FLOATS * 4)              // 114048

__global__ __launch_bounds__(256) void attn_kernel(
    const float* __restrict__ qkv, float* __restrict__ out)
{
    extern __shared__ float sm[];
    float (*Qs)[65]  = (float(*)[65])(sm);
    float (*Ks)[65]  = (float(*)[65])(sm + 32 * 65);
    float (*Vs)[65]  = (float(*)[65])(sm + 32 * 65 + 160 * 65);
    float (*P)[168]  = (float(*)[168])(sm + 32 * 65 + 2 * 160 * 65);
    float (*red)[8]  = (float(*)[8])(sm + 32 * 65 + 2 * 160 * 65 + 32 * 168);

    const int qt  = blockIdx.x;
    const int hh  = blockIdx.y;
    const int b   = blockIdx.z;
    const int tid = threadIdx.x;
    const int l0  = qt * QT;
    const int k0  = l0 - 64;

    // Load Q tile
    for (int idx = tid; idx < QT * 64; idx += 256) {
        int q = idx >> 6, d = idx & 63;
        Qs[q][d] = qkv[((size_t)(b * LL + l0 + q)) * (3 * DD) + hh * 64 + d];
    }
    // Load K/V window (zero outside sequence)
    for (int idx = tid; idx < KW * 64; idx += 256) {
        int kk = idx >> 6, d = idx & 63;
        int kg = k0 + kk;
        float kv = 0.f, vv = 0.f;
        if (kg >= 0 && kg < LL) {
            size_t base = ((size_t)(b * LL + kg)) * (3 * DD) + hh * 64 + d;
            kv = qkv[base + DD];
            vv = qkv[base + 2 * DD];
        }
        Ks[kk][d] = kv;
        Vs[kk][d] = vv;
    }
    __syncthreads();

    // Phase 2: scores for all (q, kk) pairs
    #pragma unroll 1
    for (int i = 0; i < (QT * KW) / 256; i++) {
        int pid = tid + i * 256;
        int q = pid / KW;
        int kk = pid - q * KW;
        int ql = l0 + q, kg = k0 + kk;
        int dl = ql - kg;
        float s = -1e30f;
        if (kg >= 0 && kg < LL && dl >= -64 && dl <= 64) {
            float dot = 0.f;
            #pragma unroll
            for (int d = 0; d < 64; d++)
                dot = fmaf(Qs[q][d], Ks[kk][d], dot);
            s = dot * 0.125f;   // 1/sqrt(64)
        }
        P[q][kk] = s;
    }
    __syncthreads();

    // Phase 3: softmax (8 threads per query)
    const int q    = tid >> 3;
    const int part = tid & 7;
    float m = -1e30f;
    for (int kk = part; kk < KW; kk += 8) m = fmaxf(m, P[q][kk]);
    red[q][part] = m;
    __syncthreads();
    float mq = red[q][0];
    #pragma unroll
    for (int j = 1; j < 8; j++) mq = fmaxf(mq, red[q][j]);
    __syncthreads();
    float ssum = 0.f;
    for (int kk = part; kk < KW; kk += 8) {
        float sc = P[q][kk];
        float e = (sc > -1e29f) ? __expf(sc - mq) : 0.f;
        P[q][kk] = e;
        ssum += e;
    }
    red[q][part] = ssum;
    __syncthreads();
    float tot = 0.f;
    #pragma unroll
    for (int j = 0; j < 8; j++) tot += red[q][j];
    float rinv = 1.f / tot;

    // Phase 4: P @ V, 8 dims per thread
    float o[8] = {0, 0, 0, 0, 0, 0, 0, 0};
    for (int kk = 0; kk < KW; kk++) {
        float p = P[q][kk];
        #pragma unroll
        for (int d2 = 0; d2 < 8; d2++)
            o[d2] = fmaf(p, Vs[kk][part * 8 + d2], o[d2]);
    }
    size_t obase = ((size_t)(b * LL + l0 + q)) * DD + hh * 64 + part * 8;
    #pragma unroll
    for (int d2 = 0; d2 < 8; d2++)
        out[obase + d2] = o[d2] * rinv;
}

// ---------------------------------------------------------------------------
// Fused residual add + LayerNorm (in place on h). delta may be null.
// One block per row, 256 threads, D <= 768.
// ---------------------------------------------------------------------------
__global__ __launch_bounds__(256) void add_ln_kernel(
    float* __restrict__ h, const float* __restrict__ delta,
    const float* __restrict__ gam, const float* __restrict__ bta, int D)
{
    const int row = blockIdx.x;
    const int tid = threadIdx.x;
    float xv[3];
    float s = 0.f, s2 = 0.f;
    #pragma unroll
    for (int j = 0; j < 3; j++) {
        int i = tid + j * 256;
        if (i < D) {
            float v = h[(size_t)row * D + i];
            if (delta) v += delta[(size_t)row * D + i];
            xv[j] = v;
            s += v;
            s2 += v * v;
        }
    }
    // block reduction
    __shared__ float rs[8], rs2[8];
    __shared__ float sh_mean, sh_rstd;
    #pragma unroll
    for (int o = 16; o > 0; o >>= 1) {
        s  += __shfl_xor_sync(0xffffffffu, s, o);
        s2 += __shfl_xor_sync(0xffffffffu, s2, o);
    }
    if ((tid & 31) == 0) { rs[tid >> 5] = s; rs2[tid >> 5] = s2; }
    __syncthreads();
    if (tid == 0) {
        float ts = 0.f, ts2 = 0.f;
        #pragma unroll
        for (int w = 0; w < 8; w++) { ts += rs[w]; ts2 += rs2[w]; }
        float mean = ts / (float)D;
        float var = ts2 / (float)D - mean * mean;
        sh_mean = mean;
        sh_rstd = rsqrtf(var + 1e-5f);
    }
    __syncthreads();
    float mean = sh_mean, rstd = sh_rstd;
    #pragma unroll
    for (int j = 0; j < 3; j++) {
        int i = tid + j * 256;
        if (i < D)
            h[(size_t)row * D + i] = (xv[j] - mean) * rstd * gam[i] + bta[i];
    }
}

// ---------------------------------------------------------------------------
// Pooling: sum over L, split into 16 deterministic partials then reduced.
// ---------------------------------------------------------------------------
__global__ void pool_partial_kernel(const float* __restrict__ h, float* __restrict__ pp)
{
    const int c = blockIdx.x;   // chunk 0..15
    const int b = blockIdx.y;
    for (int d = threadIdx.x; d < DD; d += 256) {
        float a = 0.f;
        int l0 = c * 64;
        for (int l = l0; l < l0 + 64; l++)
            a += h[((size_t)(b * LL + l)) * DD + d];
        pp[(size_t)(b * 16 + c) * DD + d] = a;
    }
}

__global__ void pool_reduce_kernel(const float* __restrict__ pp, float* __restrict__ pool)
{
    const int b = blockIdx.x;
    for (int d = threadIdx.x; d < DD; d += 256) {
        float a = 0.f;
        #pragma unroll
        for (int c = 0; c < 16; c++)
            a += pp[(size_t)(b * 16 + c) * DD + d];
        pool[(size_t)b * DD + d] = a;
    }
}

// ---------------------------------------------------------------------------
// Final embedding: out[b,n] = relu(e[b,:] . We[n,:] + be[n])
// ---------------------------------------------------------------------------
__global__ __launch_bounds__(256) void embed_kernel(
    const float* __restrict__ e, const float* __restrict__ We,
    const float* __restrict__ be, float* __restrict__ out)
{
    const int b = blockIdx.x;
    __shared__ float es[DD];
    for (int i = threadIdx.x; i < DD; i += 256)
        es[i] = e[(size_t)b * DD + i];
    __syncthreads();
    for (int n = threadIdx.x; n < DD; n += 256) {
        const float4* wr = (const float4*)(We + (size_t)n * DD);
        const float4* er = (const float4*)es;
        float a = 0.f;
        #pragma unroll 4
        for (int d4 = 0; d4 < DD / 4; d4++) {
            float4 w = wr[d4];
            float4 ev = er[d4];
            a = fmaf(w.x, ev.x, a); a = fmaf(w.y, ev.y, a);
            a = fmaf(w.z, ev.z, a); a = fmaf(w.w, ev.w, a);
        }
        a += be[n];
        out[(size_t)b * DD + n] = fmaxf(a, 0.f);
    }
}

// ---------------------------------------------------------------------------
// Cosine similarity: one warp per batch element.
// ---------------------------------------------------------------------------
__global__ void cos_kernel(const float* __restrict__ ex, const float* __restrict__ ey,
                           float* __restrict__ out)
{
    const int w = threadIdx.x >> 5;
    const int lane = threadIdx.x & 31;
    if (w >= BB) return;
    float dot = 0.f, nx2 = 0.f, ny2 = 0.f;
    for (int d = lane; d < DD; d += 32) {
        float a = ex[(size_t)w * DD + d];
        float c = ey[(size_t)w * DD + d];
        dot = fmaf(a, c, dot);
        nx2 = fmaf(a, a, nx2);
        ny2 = fmaf(c, c, ny2);
    }
    #pragma unroll
    for (int o = 16; o > 0; o >>= 1) {
        dot += __shfl_xor_sync(0xffffffffu, dot, o);
        nx2 += __shfl_xor_sync(0xffffffffu, nx2, o);
        ny2 += __shfl_xor_sync(0xffffffffu, ny2, o);
    }
    if (lane == 0) {
        float nx = fmaxf(sqrtf(nx2), 1e-8f);
        float ny = fmaxf(sqrtf(ny2), 1e-8f);
        out[w] = dot / (nx * ny);
    }
}

// ---------------------------------------------------------------------------
// Host orchestration
// ---------------------------------------------------------------------------
static void launch_gemm(const float* A, const float* W, const float* bias,
                        float* C, int M, int N, int K, int relu)
{
    dim3 grid(N / 64, M / 128);
    gemm_kernel<<<grid, 256>>>(A, W, bias, C, M, N, K, relu);
}

extern "C" void kernel_launch(void* const* d_in, const int* in_sizes, int n_in,
                              void* d_out, int out_size)
{
    (void)in_sizes; (void)n_in; (void)out_size;
    const float* x    = (const float*)d_in[0];
    const float* y    = (const float*)d_in[3];
    const float* Wqkv = (const float*)d_in[6];
    const float* bqkv = (const float*)d_in[7];
    const float* Wo   = (const float*)d_in[8];
    const float* bo   = (const float*)d_in[9];
    const float* ln1g = (const float*)d_in[10];
    const float* ln1b = (const float*)d_in[11];
    const float* W1   = (const float*)d_in[12];
    const float* b1   = (const float*)d_in[13];
    const float* W2   = (const float*)d_in[14];
    const float* b2   = (const float*)d_in[15];
    const float* ln2g = (const float*)d_in[16];
    const float* ln2b = (const float*)d_in[17];
    const float* lneg = (const float*)d_in[18];
    const float* lneb = (const float*)d_in[19];
    const float* We   = (const float*)d_in[20];
    const float* be   = (const float*)d_in[21];
    float* out = (float*)d_out;

    float *ph, *pqkv, *pt1, *pt2, *ppp, *ppool, *pex, *pey;
    cudaGetSymbolAddress((void**)&ph,    g_h);
    cudaGetSymbolAddress((void**)&pqkv,  g_qkv);
    cudaGetSymbolAddress((void**)&pt1,   g_t1);
    cudaGetSymbolAddress((void**)&pt2,   g_t2);
    cudaGetSymbolAddress((void**)&ppp,   g_pp);
    cudaGetSymbolAddress((void**)&ppool, g_pool);
    cudaGetSymbolAddress((void**)&pex,   g_ex);
    cudaGetSymbolAddress((void**)&pey,   g_ey);

    cudaFuncSetAttribute(attn_kernel,
                         cudaFuncAttributeMaxDynamicSharedMemorySize,
                         ATTN_SMEM_BYTES);

    for (int s = 0; s < 2; s++) {
        const float* inp = s ? y : x;
        float* pe = s ? pey : pex;

        cudaMemcpyAsync(ph, inp, sizeof(float) * MTOK * DD,
                        cudaMemcpyDeviceToDevice);

        for (int l = 0; l < NLAYERS; l++) {
            // QKV projection
            launch_gemm(ph, Wqkv + (size_t)l * 3 * DD * DD, bqkv + (size_t)l * 3 * DD,
                        pqkv, MTOK, 3 * DD, DD, 0);
            // Banded attention
            attn_kernel<<<dim3(LL / QT, HH, BB), 256, ATTN_SMEM_BYTES>>>(pqkv, pt2);
            // Output projection
            launch_gemm(pt2, Wo + (size_t)l * DD * DD, bo + (size_t)l * DD,
                        pt1, MTOK, DD, DD, 0);
            // h = LN(h + attn_proj)
            add_ln_kernel<<<MTOK, 256>>>(ph, pt1, ln1g + (size_t)l * DD,
                                         ln1b + (size_t)l * DD, DD);
            // FF1 + ReLU
            launch_gemm(ph, W1 + (size_t)l * FFD * DD, b1 + (size_t)l * FFD,
                        pt1, MTOK, FFD, DD, 1);
            // FF2
            launch_gemm(pt1, W2 + (size_t)l * DD * FFD, b2 + (size_t)l * DD,
                        pt2, MTOK, DD, FFD, 0);
            // h = LN(h + ff)
            add_ln_kernel<<<MTOK, 256>>>(ph, pt2, ln2g + (size_t)l * DD,
                                         ln2b + (size_t)l * DD, DD);
        }

        pool_partial_kernel<<<dim3(16, BB), 256>>>(ph, ppp);
        pool_reduce_kernel<<<BB, 256>>>(ppp, ppool);
        add_ln_kernel<<<BB, 256>>>(ppool, (const float*)nullptr, lneg, lneb, DD);
        embed_kernel<<<BB, 256>>>(ppool, We, be, pe);
    }

    cos_kernel<<<1, 256>>>(pex, pey, out);
}